// round 3
// baseline (speedup 1.0000x reference)
#include <cuda_runtime.h>

// Morphological dilation2d, K=7, PAD=3 (zero padding, matches nn.Unfold), then ReLU.
// out[b,c,h,w] = relu( max_{i,j} ( xp[b,c,h+i,w+j] + weight[c,i,j] ) )
//
// x:      (16, 96, 128, 128) fp32   -> d_in[0]
// weight: (96, 7, 7)          fp32  -> d_in[1]
// out:    (16, 96, 128, 128) fp32   -> d_out

#define KK    7
#define PADW  3
#define HH    128
#define WW    128
#define CC    96
#define BB    16
#define SROWS 134          // 128 + 2*3 padded rows
#define SROW  136          // smem row stride in floats (16B-aligned rows, 2 spare cols stay 0)
#define NTHREADS 256

__global__ __launch_bounds__(NTHREADS)
void morph7x7_kernel(const float* __restrict__ x,
                     const float* __restrict__ wt,
                     float* __restrict__ out) {
    extern __shared__ float xs[];                 // [SROWS][SROW] zero-padded plane
    float* wsm = xs + SROWS * SROW;               // 49 weights for this channel

    const int plane = blockIdx.x;                 // b*CC + c
    const int c = plane % CC;
    const float* gx  = x   + (size_t)plane * (HH * WW);
    float*       go  = out + (size_t)plane * (HH * WW);

    const int tid = threadIdx.x;

    // ---- zero the whole padded tile (borders must be literal zeros) ----
    #pragma unroll 4
    for (int i = tid; i < SROWS * SROW; i += NTHREADS) xs[i] = 0.0f;
    if (tid < 49) wsm[tid] = wt[c * 49 + tid];
    __syncthreads();

    // ---- load interior 128x128 (float4 global loads, scalar STS due to PAD=3 offset) ----
    #pragma unroll 4
    for (int idx = tid; idx < (HH * WW) / 4; idx += NTHREADS) {
        const int row  = idx >> 5;        // 0..127
        const int col4 = idx & 31;        // 0..31
        float4 v = reinterpret_cast<const float4*>(gx)[idx];
        float* dst = &xs[(row + PADW) * SROW + PADW + col4 * 4];
        dst[0] = v.x; dst[1] = v.y; dst[2] = v.z; dst[3] = v.w;
    }
    __syncthreads();

    // ---- compute: thread tile = 8 cols x 8 rows, one output row at a time ----
    const int tx = tid & 15;              // 16 x-tiles of 8 cols
    const int ty = tid >> 4;              // 16 y-tiles of 8 rows
    const int cbase = tx * 8;             // padded col base == output col base (reads are 32B aligned)
    const int rbase = ty * 8;

    #pragma unroll 1
    for (int th = 0; th < 8; ++th) {
        const int orow = rbase + th;
        float acc[8];
        #pragma unroll
        for (int t = 0; t < 8; ++t) acc[t] = -3.402823466e38f;

        #pragma unroll
        for (int ki = 0; ki < KK; ++ki) {
            // 16 contiguous floats of padded row (need 14): 4x LDS.128, aligned
            const float4* rp = reinterpret_cast<const float4*>(&xs[(orow + ki) * SROW + cbase]);
            const float4 v0 = rp[0], v1 = rp[1], v2 = rp[2], v3 = rp[3];
            const float row[16] = {v0.x, v0.y, v0.z, v0.w,
                                   v1.x, v1.y, v1.z, v1.w,
                                   v2.x, v2.y, v2.z, v2.w,
                                   v3.x, v3.y, v3.z, v3.w};
            // stage this kernel-row's 7 weights into registers (uniform LDS)
            float wk[KK];
            #pragma unroll
            for (int kj = 0; kj < KK; ++kj) wk[kj] = wsm[ki * KK + kj];

            #pragma unroll
            for (int kj = 0; kj < KK; ++kj) {
                const float wv = wk[kj];
                #pragma unroll
                for (int t = 0; t < 8; ++t)
                    acc[t] = fmaxf(acc[t], row[kj + t] + wv);   // FADD (fma pipe) + FMNMX (alu pipe)
            }
        }

        // ReLU + store (2x STG.128, coalesced across tx)
        float4 o0, o1;
        o0.x = fmaxf(acc[0], 0.0f); o0.y = fmaxf(acc[1], 0.0f);
        o0.z = fmaxf(acc[2], 0.0f); o0.w = fmaxf(acc[3], 0.0f);
        o1.x = fmaxf(acc[4], 0.0f); o1.y = fmaxf(acc[5], 0.0f);
        o1.z = fmaxf(acc[6], 0.0f); o1.w = fmaxf(acc[7], 0.0f);
        float4* op = reinterpret_cast<float4*>(&go[orow * WW + cbase]);
        op[0] = o0;
        op[1] = o1;
    }
}

extern "C" void kernel_launch(void* const* d_in, const int* in_sizes, int n_in,
                              void* d_out, int out_size) {
    const float* x  = (const float*)d_in[0];
    const float* wt = (const float*)d_in[1];
    float* out = (float*)d_out;

    const size_t smem_bytes = (size_t)(SROWS * SROW + 64) * sizeof(float);  // ~73 KB
    cudaFuncSetAttribute(morph7x7_kernel,
                         cudaFuncAttributeMaxDynamicSharedMemorySize,
                         (int)smem_bytes);

    morph7x7_kernel<<<BB * CC, NTHREADS, smem_bytes>>>(x, wt, out);
}

// round 4
// speedup vs baseline: 1.2222x; 1.2222x over previous
#include <cuda_runtime.h>
#include <float.h>

// Morphological dilation2d, K=7, PAD=3 (zero padding = nn.Unfold), then ReLU.
// out[b,c,h,w] = max(0, max_{i,j}( xp[b,c,h+i,w+j] + weight[c,i,j] ))
// ReLU is folded into the accumulator init (acc = 0).
//
// x:      (16, 96, 128, 128) fp32 -> d_in[0]
// weight: (96, 7, 7)         fp32 -> d_in[1]

#define KK    7
#define HH    128
#define WW    128
#define CC    96
#define BB    16
#define RPC   32            // output rows per CTA
#define SR    38            // smem rows = RPC + 6
#define SROW  136           // smem row stride (floats); interior starts at col 4
#define NT    256

__global__ __launch_bounds__(NT, 4)
void morph7x7_kernel(const float* __restrict__ x,
                     const float* __restrict__ wt,
                     float* __restrict__ out) {
    __shared__ float xs[SR * SROW];     // zero-padded slab, data at cols [4,132)
    __shared__ float wsm[49];

    const int bid   = blockIdx.x;
    const int rtile = bid & 3;          // 4 row-tiles per plane
    const int plane = bid >> 2;         // b*CC + c
    const int c     = plane % CC;
    const int R0    = rtile * RPC;

    const float* gx = x   + (size_t)plane * (HH * WW);
    float*       go = out + (size_t)plane * (HH * WW);
    const int tid = threadIdx.x;

    // ---- zero slab (borders must be literal zeros), vectorized ----
    const float4 z4 = {0.f, 0.f, 0.f, 0.f};
    #pragma unroll
    for (int i = tid; i < (SR * SROW) / 4; i += NT)
        reinterpret_cast<float4*>(xs)[i] = z4;
    if (tid < 49) wsm[tid] = wt[c * 49 + tid];
    __syncthreads();

    // ---- load interior rows: global rows [g0,g1) -> smem row g+3-R0, col base 4 ----
    const int g0 = (R0 - 3 > 0) ? R0 - 3 : 0;
    const int g1 = (R0 + 35 < HH) ? R0 + 35 : HH;
    const int n4 = (g1 - g0) * 32;      // float4 count
    #pragma unroll
    for (int idx = tid; idx < n4; idx += NT) {
        const int rr = idx >> 5;
        const int c4 = idx & 31;
        const int g  = g0 + rr;
        float4 v = reinterpret_cast<const float4*>(gx + g * WW)[c4];
        reinterpret_cast<float4*>(&xs[(g + 3 - R0) * SROW + 4])[c4] = v;  // 16B aligned
    }
    __syncthreads();

    // ---- compute: thread = 8 cols x 2 rows; 8 shared padded rows loaded once ----
    const int tx    = tid & 15;
    const int ty    = tid >> 4;
    const int cbase = tx * 8;           // output col base; LDS.128-aligned reads
    const int r0    = ty * 2;           // local output rows r0, r0+1

    float acc0[8], acc1[8];
    #pragma unroll
    for (int t = 0; t < 8; ++t) { acc0[t] = 0.0f; acc1[t] = 0.0f; }  // folds ReLU

    float wprev[7];
    #pragma unroll
    for (int s = 0; s < 8; ++s) {
        // padded row r0+s serves acc0 (ki=s, s<=6) and acc1 (ki=s-1, s>=1)
        const float4* rp = reinterpret_cast<const float4*>(&xs[(r0 + s) * SROW + cbase]);
        const float4 v0 = rp[0], v1 = rp[1], v2 = rp[2], v3 = rp[3];
        const float row[16] = {v0.x, v0.y, v0.z, v0.w,
                               v1.x, v1.y, v1.z, v1.w,
                               v2.x, v2.y, v2.z, v2.w,
                               v3.x, v3.y, v3.z, v3.w};
        float wcur[7];
        if (s < 7) {
            #pragma unroll
            for (int kj = 0; kj < 7; ++kj) wcur[kj] = wsm[s * 7 + kj];  // broadcast LDS
            #pragma unroll
            for (int kj = 0; kj < 7; ++kj) {
                const float wv = wcur[kj];
                #pragma unroll
                for (int t = 0; t < 8; ++t)
                    acc0[t] = fmaxf(acc0[t], row[1 + kj + t] + wv);
            }
        }
        if (s > 0) {
            #pragma unroll
            for (int kj = 0; kj < 7; ++kj) {
                const float wv = wprev[kj];
                #pragma unroll
                for (int t = 0; t < 8; ++t)
                    acc1[t] = fmaxf(acc1[t], row[1 + kj + t] + wv);
            }
        }
        if (s < 7) {
            #pragma unroll
            for (int kj = 0; kj < 7; ++kj) wprev[kj] = wcur[kj];  // renamed away when unrolled
        }
    }

    // ---- store (already >= 0), 2x STG.128 per row ----
    float4 o0, o1;
    o0.x = acc0[0]; o0.y = acc0[1]; o0.z = acc0[2]; o0.w = acc0[3];
    o1.x = acc0[4]; o1.y = acc0[5]; o1.z = acc0[6]; o1.w = acc0[7];
    float4* op0 = reinterpret_cast<float4*>(&go[(R0 + r0) * WW + cbase]);
    op0[0] = o0; op0[1] = o1;

    o0.x = acc1[0]; o0.y = acc1[1]; o0.z = acc1[2]; o0.w = acc1[3];
    o1.x = acc1[4]; o1.y = acc1[5]; o1.z = acc1[6]; o1.w = acc1[7];
    float4* op1 = reinterpret_cast<float4*>(&go[(R0 + r0 + 1) * WW + cbase]);
    op1[0] = o0; op1[1] = o1;
}

extern "C" void kernel_launch(void* const* d_in, const int* in_sizes, int n_in,
                              void* d_out, int out_size) {
    const float* x  = (const float*)d_in[0];
    const float* wt = (const float*)d_in[1];
    float* out = (float*)d_out;
    morph7x7_kernel<<<BB * CC * 4, NT>>>(x, wt, out);
}

// round 5
// speedup vs baseline: 1.5832x; 1.2954x over previous
#include <cuda_runtime.h>
#include <cuda_fp16.h>

// Morphological dilation2d, K=7, PAD=3 (zero padding = nn.Unfold), then ReLU.
// out[b,c,h,w] = max(0, max_{i,j}( xp[b,c,h+i,w+j] + weight[c,i,j] ))
// Computed in packed fp16x2 (HADD2 + HMNMX2); ReLU folded into acc init (=0).
//
// x:      (16, 96, 128, 128) fp32 -> d_in[0]
// weight: (96, 7, 7)         fp32 -> d_in[1]
// out:    fp32

#define HH    128
#define WW    128
#define CC    96
#define BB    16
#define RPC   32            // output rows per CTA
#define SR    38            // smem rows = RPC + 6
#define SROWH 136           // smem row stride in HALVES (272B = 17*16B)
#define NT    256

// smem layout per row (halves): S[0..3]=0 pad, S[4+k]=x[k] (k<128), S[132..135]=0.
// Padded-coords P[p] (p in [0,134)) maps to S[p+1]; taps for output w are S[w+1 .. w+7].

__device__ __forceinline__ __half2 u2h(unsigned u) { return *reinterpret_cast<__half2*>(&u); }

__global__ __launch_bounds__(NT, 4)
void morph7x7_h2_kernel(const float* __restrict__ x,
                        const float* __restrict__ wt,
                        float* __restrict__ out) {
    __shared__ __half xs[SR * SROWH];
    __shared__ unsigned wsm2[49];           // half2 broadcast (w,w) per tap

    const int bid   = blockIdx.x;
    const int rtile = bid & 3;
    const int plane = bid >> 2;             // b*CC + c
    const int c     = plane % CC;
    const int R0    = rtile * RPC;

    const float* gx = x   + (size_t)plane * (HH * WW);
    float*       go = out + (size_t)plane * (HH * WW);
    const int tid = threadIdx.x;

    // ---- zero slab (borders must be literal zeros) ----
    const uint4 z4 = {0u, 0u, 0u, 0u};
    #pragma unroll
    for (int i = tid; i < (SR * SROWH) / 8; i += NT)
        reinterpret_cast<uint4*>(xs)[i] = z4;
    if (tid < 49) {
        __half hw = __float2half_rn(wt[c * 49 + tid]);
        __half2 w2 = __half2half2(hw);
        wsm2[tid] = *reinterpret_cast<unsigned*>(&w2);
    }
    __syncthreads();

    // ---- load interior rows [g0,g1), convert fp32->fp16, data at half-col 4 ----
    const int g0 = (R0 - 3 > 0) ? R0 - 3 : 0;
    const int g1 = (R0 + 35 < HH) ? R0 + 35 : HH;
    const int n4 = (g1 - g0) * 32;          // float4 count
    #pragma unroll
    for (int idx = tid; idx < n4; idx += NT) {
        const int rr = idx >> 5;
        const int c4 = idx & 31;
        const int g  = g0 + rr;
        float4 v = reinterpret_cast<const float4*>(gx + g * WW)[c4];
        __half2 p0 = __floats2half2_rn(v.x, v.y);
        __half2 p1 = __floats2half2_rn(v.z, v.w);
        // half-col 4 + 4*c4 -> half2 index 2 + 2*c4, 8B aligned
        __half2* dst = reinterpret_cast<__half2*>(&xs[(g + 3 - R0) * SROWH + 4 + c4 * 4]);
        dst[0] = p0;
        dst[1] = p1;
    }
    __syncthreads();

    // ---- compute: thread = 8 cols x 2 rows ----
    const int tx    = tid & 15;
    const int ty    = tid >> 4;
    const int cbase = tx * 8;               // output col base; reads S[cbase..cbase+15], 16B aligned
    const int r0    = ty * 2;

    __half2 acc0[4], acc1[4];
    const __half2 h2z = __float2half2_rn(0.0f);
    #pragma unroll
    for (int p = 0; p < 4; ++p) { acc0[p] = h2z; acc1[p] = h2z; }   // folds ReLU

    unsigned wprev[7];

    #pragma unroll
    for (int s = 0; s < 8; ++s) {
        // r[idx] = S[cbase+idx]; h[m] = (r[2m], r[2m+1]); sft[m] = (r[2m+1], r[2m+2])
        const uint4* rp = reinterpret_cast<const uint4*>(&xs[(r0 + s) * SROWH + cbase]);
        const uint4 a = rp[0], b = rp[1];
        unsigned h[8] = {a.x, a.y, a.z, a.w, b.x, b.y, b.z, b.w};
        unsigned sft[7];
        #pragma unroll
        for (int m = 0; m < 7; ++m) sft[m] = __byte_perm(h[m], h[m + 1], 0x5432);

        unsigned wcur[7];
        if (s < 7) {
            #pragma unroll
            for (int j = 0; j < 7; ++j) wcur[j] = wsm2[s * 7 + j];   // broadcast LDS

            // tap j, output pair p: pair = (r[1+j+2p], r[2+j+2p])
            //   j even -> sft[j/2 + p];  j odd -> h[(j+1)/2 + p]
            #pragma unroll
            for (int j = 0; j < 7; ++j) {
                const __half2 wv = u2h(wcur[j]);
                #pragma unroll
                for (int p = 0; p < 4; ++p) {
                    const __half2 tap = (j & 1) ? u2h(h[((j + 1) >> 1) + p])
                                                : u2h(sft[(j >> 1) + p]);
                    acc0[p] = __hmax2(acc0[p], __hadd2(tap, wv));
                }
            }
        }
        if (s > 0) {
            #pragma unroll
            for (int j = 0; j < 7; ++j) {
                const __half2 wv = u2h(wprev[j]);
                #pragma unroll
                for (int p = 0; p < 4; ++p) {
                    const __half2 tap = (j & 1) ? u2h(h[((j + 1) >> 1) + p])
                                                : u2h(sft[(j >> 1) + p]);
                    acc1[p] = __hmax2(acc1[p], __hadd2(tap, wv));
                }
            }
        }
        if (s < 7) {
            #pragma unroll
            for (int j = 0; j < 7; ++j) wprev[j] = wcur[j];          // renamed when unrolled
        }
    }

    // ---- convert fp16->fp32, store 2x STG.128 per row ----
    {
        float2 f0 = __half22float2(acc0[0]);
        float2 f1 = __half22float2(acc0[1]);
        float2 f2 = __half22float2(acc0[2]);
        float2 f3 = __half22float2(acc0[3]);
        float4* op = reinterpret_cast<float4*>(&go[(R0 + r0) * WW + cbase]);
        op[0] = make_float4(f0.x, f0.y, f1.x, f1.y);
        op[1] = make_float4(f2.x, f2.y, f3.x, f3.y);
    }
    {
        float2 f0 = __half22float2(acc1[0]);
        float2 f1 = __half22float2(acc1[1]);
        float2 f2 = __half22float2(acc1[2]);
        float2 f3 = __half22float2(acc1[3]);
        float4* op = reinterpret_cast<float4*>(&go[(R0 + r0 + 1) * WW + cbase]);
        op[0] = make_float4(f0.x, f0.y, f1.x, f1.y);
        op[1] = make_float4(f2.x, f2.y, f3.x, f3.y);
    }
}

extern "C" void kernel_launch(void* const* d_in, const int* in_sizes, int n_in,
                              void* d_out, int out_size) {
    const float* x  = (const float*)d_in[0];
    const float* wt = (const float*)d_in[1];
    float* out = (float*)d_out;
    morph7x7_h2_kernel<<<BB * CC * 4, NT>>>(x, wt, out);
}

// round 6
// speedup vs baseline: 1.6338x; 1.0320x over previous
#include <cuda_runtime.h>
#include <cuda_fp16.h>

// Morphological dilation2d, K=7, PAD=3 (zero padding = nn.Unfold), then ReLU.
// out[b,c,h,w] = max(0, max_{i,j}( xp[b,c,h+i,w+j] + weight[c,i,j] ))
// Packed fp16x2 (HADD2 + HMNMX2); ReLU folded into acc init (=0).
// Software-pipelined: next row's data + next kernel-row's weights prefetched
// into registers while computing the current row.
//
// x:      (16, 96, 128, 128) fp32 -> d_in[0]
// weight: (96, 7, 7)         fp32 -> d_in[1]
// out:    fp32

#define HH    128
#define WW    128
#define CC    96
#define BB    16
#define RPC   32            // output rows per CTA
#define SR    38            // smem rows = RPC + 6
#define SROWH 136           // smem row stride in HALVES (272B)
#define NT    256

__device__ __forceinline__ __half2 u2h(unsigned u) { return *reinterpret_cast<__half2*>(&u); }

__global__ __launch_bounds__(NT, 4)
void morph7x7_h2_kernel(const float* __restrict__ x,
                        const float* __restrict__ wt,
                        float* __restrict__ out) {
    __shared__ __half xs[SR * SROWH];
    __shared__ unsigned wsm2[49];           // half2 broadcast (w,w) per tap

    const int bid   = blockIdx.x;
    const int rtile = bid & 3;
    const int plane = bid >> 2;             // b*CC + c
    const int c     = plane % CC;
    const int R0    = rtile * RPC;

    const float* gx = x   + (size_t)plane * (HH * WW);
    float*       go = out + (size_t)plane * (HH * WW);
    const int tid = threadIdx.x;

    // ---- zero slab (borders must be literal zeros) ----
    const uint4 z4 = {0u, 0u, 0u, 0u};
    #pragma unroll
    for (int i = tid; i < (SR * SROWH) / 8; i += NT)
        reinterpret_cast<uint4*>(xs)[i] = z4;
    if (tid < 49) {
        __half hw = __float2half_rn(wt[c * 49 + tid]);
        __half2 w2 = __half2half2(hw);
        wsm2[tid] = *reinterpret_cast<unsigned*>(&w2);
    }
    __syncthreads();

    // ---- load interior rows [g0,g1), fp32 -> fp16, data at half-col 4 ----
    const int g0 = (R0 - 3 > 0) ? R0 - 3 : 0;
    const int g1 = (R0 + 35 < HH) ? R0 + 35 : HH;
    const int n4 = (g1 - g0) * 32;          // float4 count
    #pragma unroll
    for (int idx = tid; idx < n4; idx += NT) {
        const int rr = idx >> 5;
        const int c4 = idx & 31;
        const int g  = g0 + rr;
        float4 v = reinterpret_cast<const float4*>(gx + g * WW)[c4];
        __half2 p0 = __floats2half2_rn(v.x, v.y);
        __half2 p1 = __floats2half2_rn(v.z, v.w);
        __half2* dst = reinterpret_cast<__half2*>(&xs[(g + 3 - R0) * SROWH + 4 + c4 * 4]);
        dst[0] = p0;
        dst[1] = p1;
    }
    __syncthreads();

    // ---- compute: thread = 8 cols x 2 rows, software-pipelined over 8 rows ----
    const int tx    = tid & 15;
    const int ty    = tid >> 4;
    const int cbase = tx * 8;               // output col base; LDS.128-aligned reads
    const int r0    = ty * 2;

    // S[0..3]=0 pad; taps for output col w are S[w+1 .. w+7].
    const uint4* rbase = reinterpret_cast<const uint4*>(&xs[r0 * SROWH + cbase]);
    const int rstride4 = SROWH / 8;         // uint4 per smem row = 17

    __half2 acc0[4], acc1[4];
    const __half2 h2z = __float2half2_rn(0.0f);
    #pragma unroll
    for (int p = 0; p < 4; ++p) { acc0[p] = h2z; acc1[p] = h2z; }   // folds ReLU

    // prime pipeline: row 0 data + weight row 0
    uint4 A = rbase[0];
    uint4 B = rbase[1];
    unsigned wcur[7], wprev[7];
    #pragma unroll
    for (int j = 0; j < 7; ++j) { wcur[j] = wsm2[j]; wprev[j] = 0u; }

    #pragma unroll
    for (int s = 0; s < 8; ++s) {
        unsigned h[8] = {A.x, A.y, A.z, A.w, B.x, B.y, B.z, B.w};

        // ---- prefetch next row + next weight row BEFORE compute ----
        if (s < 7) {
            A = rbase[(s + 1) * rstride4];
            B = rbase[(s + 1) * rstride4 + 1];
        }
        unsigned wnext[7];
        if (s < 6) {
            #pragma unroll
            for (int j = 0; j < 7; ++j) wnext[j] = wsm2[(s + 1) * 7 + j];
        }

        unsigned sft[7];
        #pragma unroll
        for (int m = 0; m < 7; ++m) sft[m] = __byte_perm(h[m], h[m + 1], 0x5432);

        // tap j, output pair p: taps = j even -> sft[j/2+p], j odd -> h[(j+1)/2+p]
        // acc0 uses weight row s (s<7); acc1 uses weight row s-1 (s>0). Interleaved.
        #pragma unroll
        for (int j = 0; j < 7; ++j) {
            const __half2 w0 = u2h(wcur[j]);
            const __half2 w1 = u2h(wprev[j]);
            #pragma unroll
            for (int p = 0; p < 4; ++p) {
                const __half2 tap = (j & 1) ? u2h(h[((j + 1) >> 1) + p])
                                            : u2h(sft[(j >> 1) + p]);
                if (s < 7) acc0[p] = __hmax2(acc0[p], __hadd2(tap, w0));
                if (s > 0) acc1[p] = __hmax2(acc1[p], __hadd2(tap, w1));
            }
        }

        // rotate weight rows (register renaming under full unroll)
        #pragma unroll
        for (int j = 0; j < 7; ++j) wprev[j] = wcur[j];
        if (s < 6) {
            #pragma unroll
            for (int j = 0; j < 7; ++j) wcur[j] = wnext[j];
        }
    }

    // ---- convert fp16 -> fp32, store 2x STG.128 per row ----
    {
        float2 f0 = __half22float2(acc0[0]);
        float2 f1 = __half22float2(acc0[1]);
        float2 f2 = __half22float2(acc0[2]);
        float2 f3 = __half22float2(acc0[3]);
        float4* op = reinterpret_cast<float4*>(&go[(R0 + r0) * WW + cbase]);
        op[0] = make_float4(f0.x, f0.y, f1.x, f1.y);
        op[1] = make_float4(f2.x, f2.y, f3.x, f3.y);
    }
    {
        float2 f0 = __half22float2(acc1[0]);
        float2 f1 = __half22float2(acc1[1]);
        float2 f2 = __half22float2(acc1[2]);
        float2 f3 = __half22float2(acc1[3]);
        float4* op = reinterpret_cast<float4*>(&go[(R0 + r0 + 1) * WW + cbase]);
        op[0] = make_float4(f0.x, f0.y, f1.x, f1.y);
        op[1] = make_float4(f2.x, f2.y, f3.x, f3.y);
    }
}

extern "C" void kernel_launch(void* const* d_in, const int* in_sizes, int n_in,
                              void* d_out, int out_size) {
    const float* x  = (const float*)d_in[0];
    const float* wt = (const float*)d_in[1];
    float* out = (float*)d_out;
    morph7x7_h2_kernel<<<BB * CC * 4, NT>>>(x, wt, out);
}